// round 3
// baseline (speedup 1.0000x reference)
#include <cuda_runtime.h>
#include <cstdint>
#include <cmath>

typedef unsigned long long ull;

#define NB   8
#define NI   8192
#define IDIM 180
#define ADIM 1536
#define SDIM 1536
#define NS   64

// ----------------------------- device scratch -------------------------------
__device__ float g_Mpart[4 * IDIM * ADIM];      // split-K partials for M = Wq @ Wk^T
__device__ float g_M[IDIM * ADIM];              // 180 x 1536
__device__ float g_Tpart[64 * IDIM * NS];       // split-K partials for T[b] = M @ slots^T
__device__ float g_Tt[NB * NS * IDIM];          // transposed+scaled: Tt[b][s][d]
__device__ float g_Gpart[64 * NS * NS];         // split-K partials for G[b] = slots slots^T
__device__ float g_G[NB * NS * NS];
__device__ float g_m[NB * NS];                  // slot row means
__device__ float g_stats[2 * NB * NI];          // [0]: mu2, [1]: rstd2 per output row

// ----------------------------- f32x2 helpers --------------------------------
__device__ __forceinline__ ull pack2(float a) {
    ull u;
    asm("mov.b64 %0, {%1, %1};" : "=l"(u) : "f"(a));
    return u;
}
__device__ __forceinline__ ull fma2(ull a, ull b, ull c) {
    ull d;
    asm("fma.rn.f32x2 %0, %1, %2, %3;" : "=l"(d) : "l"(a), "l"(b), "l"(c));
    return d;
}
__device__ __forceinline__ float2 unpack2(ull u) {
    float lo, hi;
    asm("mov.b64 {%0, %1}, %2;" : "=f"(lo), "=f"(hi) : "l"(u));
    return make_float2(lo, hi);
}

__device__ __forceinline__ float wsum(float v) {
    #pragma unroll
    for (int o = 16; o > 0; o >>= 1) v += __shfl_xor_sync(0xffffffffu, v, o);
    return v;
}
__device__ __forceinline__ float wmax(float v) {
    #pragma unroll
    for (int o = 16; o > 0; o >>= 1) v = fmaxf(v, __shfl_xor_sync(0xffffffffu, v, o));
    return v;
}

// ----------------------- generic NT GEMM, split-K partials ------------------
// Cp[z][m*N+n] = sum_{k in chunk z%nsplit} A[batch][m][k] * B[batch][n][k]
__global__ void __launch_bounds__(256) gemm_nt(
    const float* __restrict__ A, const float* __restrict__ B, float* __restrict__ Cp,
    int M, int N, int Kchunk, int lda, int ldb,
    long long aBS, long long bBS, int nsplit)
{
    int z = blockIdx.z;
    int kk = z % nsplit;
    int batch = z / nsplit;
    A += (long long)batch * aBS + (long long)kk * Kchunk;
    B += (long long)batch * bBS + (long long)kk * Kchunk;
    Cp += (long long)z * M * N;

    int m0 = blockIdx.x * 64, n0 = blockIdx.y * 64;
    __shared__ __align__(16) float As[16][68];
    __shared__ __align__(16) float Bs[16][68];

    int tid = threadIdx.x;
    int tr = tid >> 4, tc = tid & 15;
    int lr = tid >> 2, lq = tid & 3;

    float acc[4][4] = {};

    for (int kb = 0; kb < Kchunk; kb += 16) {
        __syncthreads();
        float4 av = make_float4(0.f, 0.f, 0.f, 0.f);
        if (m0 + lr < M)
            av = *(const float4*)&A[(long long)(m0 + lr) * lda + kb + 4 * lq];
        As[4 * lq + 0][lr] = av.x; As[4 * lq + 1][lr] = av.y;
        As[4 * lq + 2][lr] = av.z; As[4 * lq + 3][lr] = av.w;
        float4 bv = make_float4(0.f, 0.f, 0.f, 0.f);
        if (n0 + lr < N)
            bv = *(const float4*)&B[(long long)(n0 + lr) * ldb + kb + 4 * lq];
        Bs[4 * lq + 0][lr] = bv.x; Bs[4 * lq + 1][lr] = bv.y;
        Bs[4 * lq + 2][lr] = bv.z; Bs[4 * lq + 3][lr] = bv.w;
        __syncthreads();
        #pragma unroll
        for (int k = 0; k < 16; ++k) {
            float4 a4 = *(const float4*)&As[k][4 * tr];
            float4 b4 = *(const float4*)&Bs[k][4 * tc];
            float a[4] = {a4.x, a4.y, a4.z, a4.w};
            float b[4] = {b4.x, b4.y, b4.z, b4.w};
            #pragma unroll
            for (int i = 0; i < 4; ++i)
                #pragma unroll
                for (int j = 0; j < 4; ++j)
                    acc[i][j] = fmaf(a[i], b[j], acc[i][j]);
        }
    }
    #pragma unroll
    for (int i = 0; i < 4; ++i)
        #pragma unroll
        for (int j = 0; j < 4; ++j) {
            int m = m0 + 4 * tr + i, n = n0 + 4 * tc + j;
            if (m < M && n < N) Cp[(long long)m * N + n] = acc[i][j];
        }
}

// -------------------------- split-K reduce kernels --------------------------
__global__ void reduce_bt(const float* __restrict__ part, float* __restrict__ out,
                          int nper, int nparts)
{
    int b = blockIdx.y;
    int i = blockIdx.x * 256 + threadIdx.x;
    if (i >= nper) return;
    const float* p = part + (long long)b * nparts * nper + i;
    float s = 0.f;
    for (int k = 0; k < nparts; ++k) s += p[(long long)k * nper];
    out[(long long)b * nper + i] = s;
}

__global__ void reduce_T(float scale)
{
    int b = blockIdx.y;
    int i = blockIdx.x * 256 + threadIdx.x;
    if (i >= IDIM * NS) return;
    int s = i / IDIM, d = i % IDIM;
    const float* p = g_Tpart + (long long)b * 8 * (IDIM * NS) + d * NS + s;
    float acc = 0.f;
    #pragma unroll
    for (int k = 0; k < 8; ++k) acc += p[(long long)k * (IDIM * NS)];
    g_Tt[(long long)b * (NS * IDIM) + i] = acc * scale;   // Tt[b][s][d]
}

__global__ void slot_means(const float* __restrict__ slots)
{
    int b = blockIdx.x;
    int warp = threadIdx.x >> 5, lane = threadIdx.x & 31;
    for (int s = warp; s < NS; s += 8) {
        const float* r = slots + ((long long)b * NS + s) * SDIM;
        float acc = 0.f;
        for (int d = lane; d < SDIM; d += 32) acc += r[d];
        acc = wsum(acc);
        if (lane == 0) g_m[b * NS + s] = acc * (1.0f / SDIM);
    }
}

// ----------------- dots + softmax + LN2-stats fused kernel ------------------
// grid (NI/32, NB), block 256. Dynamic smem layout (floats):
#define D_TT   0            // 64 x 185
#define D_G    11840        // 64 x 65
#define D_M    16000        // 64
#define D_G1   16064        // 184
#define D_B1   16248        // 184
#define D_XN   16432        // 8 warps x 4 rows x 184
#define D_W    22320        // 8 warps x 4 rows x 64
#define DOTS_SMEM_FLOATS 24368
#define DOTS_SMEM_BYTES  (DOTS_SMEM_FLOATS * 4)

__global__ void __launch_bounds__(256) dots_kernel(
    const float* __restrict__ x, const float* __restrict__ g1v,
    const float* __restrict__ b1v, float* __restrict__ out_w)
{
    extern __shared__ float sm[];
    int tid = threadIdx.x;
    int b = blockIdx.y;

    for (int i = tid; i < IDIM * NS; i += 256) {
        int s = i / IDIM, d = i % IDIM;
        sm[D_TT + s * 185 + d] = g_Tt[(long long)b * (NS * IDIM) + i];
    }
    for (int i = tid; i < NS * NS; i += 256) {
        int s = i >> 6, c = i & 63;
        sm[D_G + s * 65 + c] = g_G[(long long)b * (NS * NS) + i];
    }
    if (tid < NS) sm[D_M + tid] = g_m[b * NS + tid];
    if (tid < IDIM) { sm[D_G1 + tid] = g1v[tid]; sm[D_B1 + tid] = b1v[tid]; }
    __syncthreads();

    int warp = tid >> 5, lane = tid & 31;
    long long rowbase = (long long)blockIdx.x * 32 + warp * 4;
    long long gbase = (long long)b * NI + rowbase;
    float* xnW = sm + D_XN + warp * (4 * 184);
    float* wW  = sm + D_W  + warp * (4 * 64);

    // phase 1: layernorm of 4 rows
    #pragma unroll
    for (int j = 0; j < 4; ++j) {
        const float* xr = x + (gbase + j) * IDIM;
        float xv[6];
        float s1 = 0.f, s2 = 0.f;
        #pragma unroll
        for (int t = 0; t < 6; ++t) {
            int d = lane + 32 * t;
            float v = (d < IDIM) ? xr[d] : 0.f;
            xv[t] = v; s1 += v; s2 = fmaf(v, v, s2);
        }
        s1 = wsum(s1); s2 = wsum(s2);
        float mu = s1 * (1.0f / IDIM);
        float rs = rsqrtf(s2 * (1.0f / IDIM) - mu * mu + 1e-5f);
        #pragma unroll
        for (int t = 0; t < 6; ++t) {
            int d = lane + 32 * t;
            if (d < IDIM)
                xnW[j * 184 + d] = (xv[t] - mu) * rs * sm[D_G1 + d] + sm[D_B1 + d];
        }
    }
    __syncwarp();

    // phase 2: dots for s = lane, lane+32 over 4 rows
    float a0[4] = {0.f, 0.f, 0.f, 0.f}, a1[4] = {0.f, 0.f, 0.f, 0.f};
    const float* t0p = sm + D_TT + lane * 185;
    const float* t1p = t0p + 32 * 185;
    #pragma unroll 4
    for (int d = 0; d < IDIM; ++d) {
        float t0 = t0p[d], t1 = t1p[d];
        #pragma unroll
        for (int j = 0; j < 4; ++j) {
            float xv = xnW[j * 184 + d];
            a0[j] = fmaf(xv, t0, a0[j]);
            a1[j] = fmaf(xv, t1, a1[j]);
        }
    }

    // phase 3: softmax, write w, mu2
    float w1a[4], w2a[4], mu2a[4];
    #pragma unroll
    for (int j = 0; j < 4; ++j) {
        float mx = wmax(fmaxf(a0[j], a1[j]));
        float e1 = __expf(a0[j] - mx), e2 = __expf(a1[j] - mx);
        float sum = wsum(e1 + e2);
        float inv = 1.0f / sum;
        float w1 = e1 * inv, w2 = e2 * inv;
        float* wo = out_w + (gbase + j) * NS;
        wo[lane] = w1; wo[lane + 32] = w2;
        wW[j * 64 + lane] = w1; wW[j * 64 + lane + 32] = w2;
        w1a[j] = w1; w2a[j] = w2;
        mu2a[j] = wsum(w1 * sm[D_M + lane] + w2 * sm[D_M + lane + 32]);
    }
    __syncwarp();

    // phase 4: ssq = w^T G w  -> rstd2
    const float* gr0 = sm + D_G + lane * 65;
    const float* gr1 = gr0 + 32 * 65;
    #pragma unroll
    for (int j = 0; j < 4; ++j) {
        float gw1 = 0.f, gw2 = 0.f;
        #pragma unroll 4
        for (int sp = 0; sp < NS; ++sp) {
            float ws = wW[j * 64 + sp];
            gw1 = fmaf(gr0[sp], ws, gw1);
            gw2 = fmaf(gr1[sp], ws, gw2);
        }
        float ssq = wsum(w1a[j] * gw1 + w2a[j] * gw2);
        float mu2 = mu2a[j];
        float rs2 = rsqrtf(ssq * (1.0f / SDIM) - mu2 * mu2 + 1e-5f);
        if (lane == 0) {
            g_stats[gbase + j] = mu2;
            g_stats[(long long)NB * NI + gbase + j] = rs2;
        }
    }
}

// --------------------- output GEMM: s = LN(w @ slots) -----------------------
// grid (SDIM/256, NI/64, NB), block 256. Tile 64 rows x 256 cols, f32x2 FMA.
#define O_S    0        // slots tile 64 x 256
#define O_WT   16384    // w transposed 64 s x 68
#define O_MU   20736    // 64
#define O_RS   20800    // 64
#define O_G2   20864    // 256
#define O_B2   21120    // 256
#define OUT_SMEM_FLOATS 21376
#define OUT_SMEM_BYTES  (OUT_SMEM_FLOATS * 4)

__global__ void __launch_bounds__(256) out_kernel(
    const float* __restrict__ slots, const float* __restrict__ g2v,
    const float* __restrict__ b2v, const float* __restrict__ w_in,
    float* __restrict__ out_s)
{
    extern __shared__ float sm[];
    int tid = threadIdx.x;
    int b = blockIdx.z;
    int d0 = blockIdx.x * 256;
    long long ibase = (long long)b * NI + (long long)blockIdx.y * 64;

    // slots tile (float4 coalesced)
    for (int idx = tid; idx < 4096; idx += 256) {
        int s = idx >> 6, c4 = idx & 63;
        float4 v = *(const float4*)&slots[((long long)b * NS + s) * SDIM + d0 + 4 * c4];
        *(float4*)&sm[O_S + s * 256 + 4 * c4] = v;
    }
    // w transpose: wt[s][r]
    for (int idx = tid; idx < 4096; idx += 256) {
        int r = idx >> 6, s = idx & 63;
        sm[O_WT + s * 68 + r] = w_in[(ibase + r) * NS + s];
    }
    if (tid < 64) {
        sm[O_MU + tid] = g_stats[ibase + tid];
        sm[O_RS + tid] = g_stats[(long long)NB * NI + ibase + tid];
    }
    sm[O_G2 + tid] = g2v[d0 + tid];
    sm[O_B2 + tid] = b2v[d0 + tid];
    __syncthreads();

    int tr = tid >> 4, tc = tid & 15;
    ull acc[4][8] = {};
    const float* wtp = sm + O_WT + 4 * tr;
    const float* bsp = sm + O_S + 16 * tc;

    #pragma unroll 1
    for (int s = 0; s < NS; ++s) {
        float4 av = *(const float4*)(wtp + s * 68);
        ull aa[4] = {pack2(av.x), pack2(av.y), pack2(av.z), pack2(av.w)};
        const ulonglong2* bp = (const ulonglong2*)(bsp + s * 256);
        ulonglong2 q0 = bp[0], q1 = bp[1], q2 = bp[2], q3 = bp[3];
        ull bb[8] = {q0.x, q0.y, q1.x, q1.y, q2.x, q2.y, q3.x, q3.y};
        #pragma unroll
        for (int r = 0; r < 4; ++r)
            #pragma unroll
            for (int j = 0; j < 8; ++j)
                acc[r][j] = fma2(aa[r], bb[j], acc[r][j]);
    }

    const ulonglong2* gpv = (const ulonglong2*)(sm + O_G2 + 16 * tc);
    const ulonglong2* bpv = (const ulonglong2*)(sm + O_B2 + 16 * tc);
    ulonglong2 gA = gpv[0], gB = gpv[1], gC = gpv[2], gD = gpv[3];
    ulonglong2 bA = bpv[0], bB = bpv[1], bC = bpv[2], bD = bpv[3];
    ull gg[8] = {gA.x, gA.y, gB.x, gB.y, gC.x, gC.y, gD.x, gD.y};
    ull b2p[8] = {bA.x, bA.y, bB.x, bB.y, bC.x, bC.y, bD.x, bD.y};

    #pragma unroll
    for (int r = 0; r < 4; ++r) {
        int row = 4 * tr + r;
        float mu = sm[O_MU + row], rs = sm[O_RS + row];
        ull pr = pack2(rs);
        ull pm = pack2(-mu * rs);
        float* op = out_s + (ibase + row) * (long long)SDIM + d0 + 16 * tc;
        #pragma unroll
        for (int j2 = 0; j2 < 4; ++j2) {
            ull y0 = fma2(fma2(acc[r][2 * j2],     pr, pm), gg[2 * j2],     b2p[2 * j2]);
            ull y1 = fma2(fma2(acc[r][2 * j2 + 1], pr, pm), gg[2 * j2 + 1], b2p[2 * j2 + 1]);
            float2 p0 = unpack2(y0), p1 = unpack2(y1);
            *(float4*)(op + 4 * j2) = make_float4(p0.x, p0.y, p1.x, p1.y);
        }
    }
}

// ------------------------------- launcher -----------------------------------
extern "C" void kernel_launch(void* const* d_in, const int* in_sizes, int n_in,
                              void* d_out, int out_size)
{
    const float* x     = (const float*)d_in[0];
    const float* slots = (const float*)d_in[1];
    const float* Wq    = (const float*)d_in[2];
    const float* Wk    = (const float*)d_in[3];
    const float* g1v   = (const float*)d_in[4];
    const float* b1v   = (const float*)d_in[5];
    const float* g2v   = (const float*)d_in[6];
    const float* b2v   = (const float*)d_in[7];

    float* out_s = (float*)d_out;
    float* out_w = out_s + (long long)NB * NI * SDIM;

    float *pMpart, *pM, *pTpart, *pGpart, *pG;
    cudaGetSymbolAddress((void**)&pMpart, g_Mpart);
    cudaGetSymbolAddress((void**)&pM,     g_M);
    cudaGetSymbolAddress((void**)&pTpart, g_Tpart);
    cudaGetSymbolAddress((void**)&pGpart, g_Gpart);
    cudaGetSymbolAddress((void**)&pG,     g_G);

    cudaFuncSetAttribute(dots_kernel, cudaFuncAttributeMaxDynamicSharedMemorySize, DOTS_SMEM_BYTES);
    cudaFuncSetAttribute(out_kernel,  cudaFuncAttributeMaxDynamicSharedMemorySize, OUT_SMEM_BYTES);

    // M = Wq @ Wk^T   (180 x 1536), split-K x4
    gemm_nt<<<dim3(3, 24, 4), 256>>>(Wq, Wk, pMpart, IDIM, ADIM, ADIM / 4,
                                     ADIM, ADIM, 0LL, 0LL, 4);
    reduce_bt<<<dim3((IDIM * ADIM + 255) / 256, 1), 256>>>(pMpart, pM, IDIM * ADIM, 4);

    // G[b] = slots slots^T (64 x 64 per batch), split-K x8
    gemm_nt<<<dim3(1, 1, 64), 256>>>(slots, slots, pGpart, NS, NS, SDIM / 8,
                                     SDIM, SDIM, (long long)NS * SDIM, (long long)NS * SDIM, 8);
    reduce_bt<<<dim3((NS * NS + 255) / 256, NB), 256>>>(pGpart, pG, NS * NS, 8);

    // T[b] = M @ slots[b]^T (180 x 64 per batch), split-K x8; Tt = scale * T^T
    gemm_nt<<<dim3(3, 1, 64), 256>>>(pM, slots, pTpart, IDIM, NS, SDIM / 8,
                                     ADIM, SDIM, 0LL, (long long)NS * SDIM, 8);
    float scale = (float)(1.0 / sqrt((double)ADIM));
    reduce_T<<<dim3((IDIM * NS + 255) / 256, NB), 256>>>(scale);

    slot_means<<<NB, 256>>>(slots);

    dots_kernel<<<dim3(NI / 32, NB), 256, DOTS_SMEM_BYTES>>>(x, g1v, b1v, out_w);

    out_kernel<<<dim3(SDIM / 256, NI / 64, NB), 256, OUT_SMEM_BYTES>>>(
        slots, g2v, b2v, out_w, out_s);
}

// round 6
// speedup vs baseline: 2.9979x; 2.9979x over previous
#include <cuda_runtime.h>
#include <cuda_bf16.h>
#include <cstdint>
#include <cmath>

typedef unsigned long long ull;

#define NB   8
#define NI   8192
#define IDIM 180
#define ADIM 1536
#define SDIM 1536
#define NS   64

// ----------------------------- device scratch -------------------------------
__device__ float g_Mpart[4 * IDIM * ADIM];
__device__ float g_M[IDIM * ADIM];
__device__ float g_Tpart[64 * IDIM * NS];
__device__ float g_Tt[NB * NS * IDIM];
__device__ float g_Gpart[64 * NS * NS];
__device__ float g_G[NB * NS * NS];
__device__ float g_m[NB * NS];
__device__ float g_stats[2 * NB * NI];
__device__ __align__(16) __nv_bfloat16 g_sThi[NB * SDIM * NS];   // slots^T hi [b][d][s]
__device__ __align__(16) __nv_bfloat16 g_sTlo[NB * SDIM * NS];   // slots^T lo
__device__ __align__(16) __nv_bfloat16 g_whi[NB * NI * NS];      // w hi [b][i][s]
__device__ __align__(16) __nv_bfloat16 g_wlo[NB * NI * NS];      // w lo

// ----------------------------- warp helpers ---------------------------------
__device__ __forceinline__ float wsum(float v) {
    #pragma unroll
    for (int o = 16; o > 0; o >>= 1) v += __shfl_xor_sync(0xffffffffu, v, o);
    return v;
}
__device__ __forceinline__ float wmax(float v) {
    #pragma unroll
    for (int o = 16; o > 0; o >>= 1) v = fmaxf(v, __shfl_xor_sync(0xffffffffu, v, o));
    return v;
}
__device__ __forceinline__ uint32_t smem_u32(const void* p) {
    uint32_t a;
    asm("{ .reg .u64 t; cvta.to.shared.u64 t, %1; cvt.u32.u64 %0, t; }" : "=r"(a) : "l"(p));
    return a;
}

// --------------------------- mma.sync helpers --------------------------------
__device__ __forceinline__ void ldm_x4(uint32_t a, uint32_t* r) {
    asm volatile("ldmatrix.sync.aligned.m8n8.x4.shared.b16 {%0,%1,%2,%3}, [%4];"
        : "=r"(r[0]), "=r"(r[1]), "=r"(r[2]), "=r"(r[3]) : "r"(a));
}
__device__ __forceinline__ void mma_bf16(float* c, const uint32_t* a, const uint32_t* b) {
    asm volatile("mma.sync.aligned.m16n8k16.row.col.f32.bf16.bf16.f32 "
        "{%0,%1,%2,%3}, {%4,%5,%6,%7}, {%8,%9}, {%0,%1,%2,%3};"
        : "+f"(c[0]), "+f"(c[1]), "+f"(c[2]), "+f"(c[3])
        : "r"(a[0]), "r"(a[1]), "r"(a[2]), "r"(a[3]), "r"(b[0]), "r"(b[1]));
}

// ----------------------- generic NT GEMM, split-K partials ------------------
__global__ void __launch_bounds__(256) gemm_nt(
    const float* __restrict__ A, const float* __restrict__ B, float* __restrict__ Cp,
    int M, int N, int Kchunk, int lda, int ldb,
    long long aBS, long long bBS, int nsplit)
{
    int z = blockIdx.z;
    int kk = z % nsplit;
    int batch = z / nsplit;
    A += (long long)batch * aBS + (long long)kk * Kchunk;
    B += (long long)batch * bBS + (long long)kk * Kchunk;
    Cp += (long long)z * M * N;

    int m0 = blockIdx.x * 64, n0 = blockIdx.y * 64;
    __shared__ __align__(16) float As[16][68];
    __shared__ __align__(16) float Bs[16][68];

    int tid = threadIdx.x;
    int tr = tid >> 4, tc = tid & 15;
    int lr = tid >> 2, lq = tid & 3;

    float acc[4][4] = {};

    for (int kb = 0; kb < Kchunk; kb += 16) {
        __syncthreads();
        float4 av = make_float4(0.f, 0.f, 0.f, 0.f);
        if (m0 + lr < M)
            av = *(const float4*)&A[(long long)(m0 + lr) * lda + kb + 4 * lq];
        As[4 * lq + 0][lr] = av.x; As[4 * lq + 1][lr] = av.y;
        As[4 * lq + 2][lr] = av.z; As[4 * lq + 3][lr] = av.w;
        float4 bv = make_float4(0.f, 0.f, 0.f, 0.f);
        if (n0 + lr < N)
            bv = *(const float4*)&B[(long long)(n0 + lr) * ldb + kb + 4 * lq];
        Bs[4 * lq + 0][lr] = bv.x; Bs[4 * lq + 1][lr] = bv.y;
        Bs[4 * lq + 2][lr] = bv.z; Bs[4 * lq + 3][lr] = bv.w;
        __syncthreads();
        #pragma unroll
        for (int k = 0; k < 16; ++k) {
            float4 a4 = *(const float4*)&As[k][4 * tr];
            float4 b4 = *(const float4*)&Bs[k][4 * tc];
            float a[4] = {a4.x, a4.y, a4.z, a4.w};
            float b[4] = {b4.x, b4.y, b4.z, b4.w};
            #pragma unroll
            for (int i = 0; i < 4; ++i)
                #pragma unroll
                for (int j = 0; j < 4; ++j)
                    acc[i][j] = fmaf(a[i], b[j], acc[i][j]);
        }
    }
    #pragma unroll
    for (int i = 0; i < 4; ++i)
        #pragma unroll
        for (int j = 0; j < 4; ++j) {
            int m = m0 + 4 * tr + i, n = n0 + 4 * tc + j;
            if (m < M && n < N) Cp[(long long)m * N + n] = acc[i][j];
        }
}

// -------------------------- split-K reduce kernels --------------------------
__global__ void reduce_bt(const float* __restrict__ part, float* __restrict__ out,
                          int nper, int nparts)
{
    int b = blockIdx.y;
    int i = blockIdx.x * 256 + threadIdx.x;
    if (i >= nper) return;
    const float* p = part + (long long)b * nparts * nper + i;
    float s = 0.f;
    for (int k = 0; k < nparts; ++k) s += p[(long long)k * nper];
    out[(long long)b * nper + i] = s;
}

__global__ void reduce_T(float scale)
{
    int b = blockIdx.y;
    int i = blockIdx.x * 256 + threadIdx.x;
    if (i >= IDIM * NS) return;
    int s = i / IDIM, d = i % IDIM;
    const float* p = g_Tpart + (long long)b * 8 * (IDIM * NS) + d * NS + s;
    float acc = 0.f;
    #pragma unroll
    for (int k = 0; k < 8; ++k) acc += p[(long long)k * (IDIM * NS)];
    g_Tt[(long long)b * (NS * IDIM) + i] = acc * scale;
}

__global__ void slot_means(const float* __restrict__ slots)
{
    int b = blockIdx.x;
    int warp = threadIdx.x >> 5, lane = threadIdx.x & 31;
    for (int s = warp; s < NS; s += 8) {
        const float* r = slots + ((long long)b * NS + s) * SDIM;
        float acc = 0.f;
        for (int d = lane; d < SDIM; d += 32) acc += r[d];
        acc = wsum(acc);
        if (lane == 0) g_m[b * NS + s] = acc * (1.0f / SDIM);
    }
}

// ----------------- slots^T bf16 hi/lo split:  sT[b][d][s] -------------------
__global__ void __launch_bounds__(256) split_slots(const float* __restrict__ slots)
{
    __shared__ float ts[64][129];
    int b = blockIdx.y;
    int d0 = blockIdx.x * 128;
    int tid = threadIdx.x;
    for (int idx = tid; idx < 64 * 128; idx += 256) {
        int s = idx >> 7, dd = idx & 127;
        ts[s][dd] = slots[((long long)b * NS + s) * SDIM + d0 + dd];
    }
    __syncthreads();
    for (int idx = tid; idx < 128 * 64; idx += 256) {
        int d = idx >> 6, s = idx & 63;
        float v = ts[s][d];
        __nv_bfloat16 h = __float2bfloat16(v);
        __nv_bfloat16 l = __float2bfloat16(v - __bfloat162float(h));
        long long o = ((long long)b * SDIM + d0 + d) * NS + s;
        g_sThi[o] = h;
        g_sTlo[o] = l;
    }
}

// ----------------- dots + softmax + LN2-stats fused kernel ------------------
#define D_TT   0            // 64 x 188
#define D_G    12032        // 64 x 65
#define D_M    16192        // 64
#define D_G1   16256        // 184
#define D_B1   16440        // 184
#define D_XN   16624        // 8 warps x 4 rows x 184
#define D_W    22512        // 8 warps x 4 rows x 64
#define DOTS_SMEM_FLOATS 24560
#define DOTS_SMEM_BYTES  (DOTS_SMEM_FLOATS * 4)

__global__ void __launch_bounds__(256) dots_kernel(
    const float* __restrict__ x, const float* __restrict__ g1v,
    const float* __restrict__ b1v, float* __restrict__ out_w)
{
    extern __shared__ float sm[];
    int tid = threadIdx.x;
    int b = blockIdx.y;

    for (int i = tid; i < IDIM * NS; i += 256) {
        int s = i / IDIM, d = i % IDIM;
        sm[D_TT + s * 188 + d] = g_Tt[(long long)b * (NS * IDIM) + i];
    }
    for (int i = tid; i < NS * NS; i += 256) {
        int s = i >> 6, c = i & 63;
        sm[D_G + s * 65 + c] = g_G[(long long)b * (NS * NS) + i];
    }
    if (tid < NS) sm[D_M + tid] = g_m[b * NS + tid];
    if (tid < IDIM) { sm[D_G1 + tid] = g1v[tid]; sm[D_B1 + tid] = b1v[tid]; }
    __syncthreads();

    int warp = tid >> 5, lane = tid & 31;
    long long rowbase = (long long)blockIdx.x * 32 + warp * 4;
    long long gbase = (long long)b * NI + rowbase;
    float* xnW = sm + D_XN + warp * (4 * 184);
    float* wW  = sm + D_W  + warp * (4 * 64);

    #pragma unroll
    for (int j = 0; j < 4; ++j) {
        const float* xr = x + (gbase + j) * IDIM;
        float xv[6];
        float s1 = 0.f, s2 = 0.f;
        #pragma unroll
        for (int t = 0; t < 6; ++t) {
            int d = lane + 32 * t;
            float v = (d < IDIM) ? xr[d] : 0.f;
            xv[t] = v; s1 += v; s2 = fmaf(v, v, s2);
        }
        s1 = wsum(s1); s2 = wsum(s2);
        float mu = s1 * (1.0f / IDIM);
        float rs = rsqrtf(s2 * (1.0f / IDIM) - mu * mu + 1e-5f);
        #pragma unroll
        for (int t = 0; t < 6; ++t) {
            int d = lane + 32 * t;
            if (d < IDIM)
                xnW[j * 184 + d] = (xv[t] - mu) * rs * sm[D_G1 + d] + sm[D_B1 + d];
        }
    }
    __syncwarp();

    float a0[4] = {0.f, 0.f, 0.f, 0.f}, a1[4] = {0.f, 0.f, 0.f, 0.f};
    const float* t0p = sm + D_TT + lane * 188;
    const float* t1p = t0p + 32 * 188;
    #pragma unroll 3
    for (int d4 = 0; d4 < IDIM; d4 += 4) {
        float4 t0 = *(const float4*)(t0p + d4);
        float4 t1 = *(const float4*)(t1p + d4);
        #pragma unroll
        for (int j = 0; j < 4; ++j) {
            float4 xv = *(const float4*)(xnW + j * 184 + d4);
            a0[j] = fmaf(xv.x, t0.x, fmaf(xv.y, t0.y, fmaf(xv.z, t0.z, fmaf(xv.w, t0.w, a0[j]))));
            a1[j] = fmaf(xv.x, t1.x, fmaf(xv.y, t1.y, fmaf(xv.z, t1.z, fmaf(xv.w, t1.w, a1[j]))));
        }
    }

    float w1a[4], w2a[4], mu2a[4];
    #pragma unroll
    for (int j = 0; j < 4; ++j) {
        float mx = wmax(fmaxf(a0[j], a1[j]));
        float e1 = __expf(a0[j] - mx), e2 = __expf(a1[j] - mx);
        float sum = wsum(e1 + e2);
        float inv = 1.0f / sum;
        float w1 = e1 * inv, w2 = e2 * inv;
        float* wo = out_w + (gbase + j) * NS;
        wo[lane] = w1; wo[lane + 32] = w2;
        __nv_bfloat16 h1 = __float2bfloat16(w1);
        __nv_bfloat16 h2 = __float2bfloat16(w2);
        long long wb = (gbase + j) * NS;
        g_whi[wb + lane] = h1;
        g_whi[wb + lane + 32] = h2;
        g_wlo[wb + lane] = __float2bfloat16(w1 - __bfloat162float(h1));
        g_wlo[wb + lane + 32] = __float2bfloat16(w2 - __bfloat162float(h2));
        wW[j * 64 + lane] = w1; wW[j * 64 + lane + 32] = w2;
        w1a[j] = w1; w2a[j] = w2;
        mu2a[j] = wsum(w1 * sm[D_M + lane] + w2 * sm[D_M + lane + 32]);
    }
    __syncwarp();

    const float* gr0 = sm + D_G + lane * 65;
    const float* gr1 = gr0 + 32 * 65;
    #pragma unroll
    for (int j = 0; j < 4; ++j) {
        float gw1 = 0.f, gw2 = 0.f;
        #pragma unroll 4
        for (int sp = 0; sp < NS; ++sp) {
            float ws = wW[j * 64 + sp];
            gw1 = fmaf(gr0[sp], ws, gw1);
            gw2 = fmaf(gr1[sp], ws, gw2);
        }
        float ssq = wsum(w1a[j] * gw1 + w2a[j] * gw2);
        float mu2 = mu2a[j];
        float rs2 = rsqrtf(ssq * (1.0f / SDIM) - mu2 * mu2 + 1e-5f);
        if (lane == 0) {
            g_stats[gbase + j] = mu2;
            g_stats[(long long)NB * NI + gbase + j] = rs2;
        }
    }
}

// ---------------- mma.sync output GEMM: s = LN(w @ slots) -------------------
// Tile: 128 i x 128 d per block, K = NS = 64 fully resident.
// A = w[i][s] row-major (hi/lo); B = sT[d][s] n-major (k contiguous) -> non-trans
// ldmatrix gives the mma.row.col B fragment directly.
// 3-term bf16 split: wh*sh + wh*sl + wl*sh accumulated in fp32.
#define OM_SWHI 0
#define OM_SWLO 18432
#define OM_SSHI 36864
#define OM_SSLO 55296
#define OM_MU   73728
#define OM_RS   74240
#define OM_GAM  74752
#define OM_BET  75264
#define OM_BYTES 75776

__global__ void __launch_bounds__(256) out_mma_kernel(
    const float* __restrict__ g2v, const float* __restrict__ b2v,
    float* __restrict__ out_s)
{
    extern __shared__ char smc[];
    int tid = threadIdx.x;
    int b = blockIdx.z;
    int i0 = blockIdx.y * 128;
    int d0 = blockIdx.x * 128;
    long long gib = (long long)b * NI + i0;

    const uint4* wh = (const uint4*)(g_whi + gib * NS);
    const uint4* wl = (const uint4*)(g_wlo + gib * NS);
    const uint4* sh = (const uint4*)(g_sThi + ((long long)b * SDIM + d0) * NS);
    const uint4* sl = (const uint4*)(g_sTlo + ((long long)b * SDIM + d0) * NS);
    #pragma unroll
    for (int it = 0; it < 4; ++it) {
        int idx = tid + 256 * it;            // 1024 uint4 per operand
        int r = idx >> 3, q = idx & 7;
        uint32_t doff = (uint32_t)r * 144 + (uint32_t)q * 16;
        *(uint4*)(smc + OM_SWHI + doff) = wh[idx];
        *(uint4*)(smc + OM_SWLO + doff) = wl[idx];
        *(uint4*)(smc + OM_SSHI + doff) = sh[idx];
        *(uint4*)(smc + OM_SSLO + doff) = sl[idx];
    }
    if (tid < 128) {
        ((float*)(smc + OM_MU))[tid]  = g_stats[gib + tid];
        ((float*)(smc + OM_RS))[tid]  = g_stats[(long long)NB * NI + gib + tid];
        ((float*)(smc + OM_GAM))[tid] = g2v[d0 + tid];
        ((float*)(smc + OM_BET))[tid] = b2v[d0 + tid];
    }
    __syncthreads();

    int wid = tid >> 5, lane = tid & 31;
    int wm = wid & 3, wn = wid >> 2;      // warp tile: 32 i x 64 d
    uint32_t sbase = smem_u32(smc);
    int trow = lane & 15;
    uint32_t tcolb = (uint32_t)(lane >> 4) * 16;   // A ldmatrix col byte offset

    float c[2][8][4];
    #pragma unroll
    for (int mi = 0; mi < 2; ++mi)
        #pragma unroll
        for (int nj = 0; nj < 8; ++nj)
            #pragma unroll
            for (int q = 0; q < 4; ++q) c[mi][nj][q] = 0.f;

    // B ldmatrix lane mapping: matrix j = lane>>3 covers
    //   n-half (j&1)*8, k-half (j>>1)*8; lane row within matrix = lane&7.
    uint32_t brow = (uint32_t)(wn * 64 + ((lane >> 3) & 1) * 8 + (lane & 7)) * 144;
    uint32_t bcolbase = (uint32_t)(lane >> 4) * 16;

    #pragma unroll
    for (int ks = 0; ks < 4; ++ks) {
        uint32_t kb = (uint32_t)ks * 32 + tcolb;
        uint32_t ah[2][4], al[2][4];
        #pragma unroll
        for (int mi = 0; mi < 2; ++mi) {
            uint32_t ra = sbase + OM_SWHI + (uint32_t)(wm * 32 + mi * 16 + trow) * 144 + kb;
            ldm_x4(ra, ah[mi]);
            ldm_x4(ra + (OM_SWLO - OM_SWHI), al[mi]);
        }
        uint32_t bcol = (uint32_t)ks * 32 + bcolbase;
        #pragma unroll
        for (int g = 0; g < 4; ++g) {
            uint32_t rb = sbase + OM_SSHI + brow + (uint32_t)(g * 16) * 144 + bcol;
            uint32_t th[4], tl[4];
            ldm_x4(rb, th);
            ldm_x4(rb + (OM_SSLO - OM_SSHI), tl);
            uint32_t bh0[2] = {th[0], th[2]}, bh1[2] = {th[1], th[3]};
            uint32_t bl0[2] = {tl[0], tl[2]}, bl1[2] = {tl[1], tl[3]};
            #pragma unroll
            for (int mi = 0; mi < 2; ++mi) {
                mma_bf16(c[mi][2 * g],     ah[mi], bh0);
                mma_bf16(c[mi][2 * g],     ah[mi], bl0);
                mma_bf16(c[mi][2 * g],     al[mi], bh0);
                mma_bf16(c[mi][2 * g + 1], ah[mi], bh1);
                mma_bf16(c[mi][2 * g + 1], ah[mi], bl1);
                mma_bf16(c[mi][2 * g + 1], al[mi], bh1);
            }
        }
    }

    // epilogue: LN + store
    const float* muP = (const float*)(smc + OM_MU);
    const float* rsP = (const float*)(smc + OM_RS);
    const float* gmP = (const float*)(smc + OM_GAM);
    const float* btP = (const float*)(smc + OM_BET);
    int grp = lane >> 2, tig = lane & 3;
    #pragma unroll
    for (int mi = 0; mi < 2; ++mi) {
        int r0 = wm * 32 + mi * 16 + grp;
        int r1 = r0 + 8;
        float mu0 = muP[r0], rs0 = rsP[r0];
        float mu1 = muP[r1], rs1 = rsP[r1];
        #pragma unroll
        for (int nj = 0; nj < 8; ++nj) {
            int col = wn * 64 + nj * 8 + 2 * tig;
            float2 gm = *(const float2*)(gmP + col);
            float2 bt = *(const float2*)(btP + col);
            float* c4 = c[mi][nj];
            float2 v0, v1;
            v0.x = (c4[0] - mu0) * rs0 * gm.x + bt.x;
            v0.y = (c4[1] - mu0) * rs0 * gm.y + bt.y;
            v1.x = (c4[2] - mu1) * rs1 * gm.x + bt.x;
            v1.y = (c4[3] - mu1) * rs1 * gm.y + bt.y;
            *(float2*)(out_s + (gib + r0) * (long long)SDIM + d0 + col) = v0;
            *(float2*)(out_s + (gib + r1) * (long long)SDIM + d0 + col) = v1;
        }
    }
}

// ------------------------------- launcher -----------------------------------
extern "C" void kernel_launch(void* const* d_in, const int* in_sizes, int n_in,
                              void* d_out, int out_size)
{
    const float* x     = (const float*)d_in[0];
    const float* slots = (const float*)d_in[1];
    const float* Wq    = (const float*)d_in[2];
    const float* Wk    = (const float*)d_in[3];
    const float* g1v   = (const float*)d_in[4];
    const float* b1v   = (const float*)d_in[5];
    const float* g2v   = (const float*)d_in[6];
    const float* b2v   = (const float*)d_in[7];

    float* out_s = (float*)d_out;
    float* out_w = out_s + (long long)NB * NI * SDIM;

    float *pMpart, *pM, *pTpart, *pGpart, *pG;
    cudaGetSymbolAddress((void**)&pMpart, g_Mpart);
    cudaGetSymbolAddress((void**)&pM,     g_M);
    cudaGetSymbolAddress((void**)&pTpart, g_Tpart);
    cudaGetSymbolAddress((void**)&pGpart, g_Gpart);
    cudaGetSymbolAddress((void**)&pG,     g_G);

    cudaFuncSetAttribute(dots_kernel, cudaFuncAttributeMaxDynamicSharedMemorySize, DOTS_SMEM_BYTES);
    cudaFuncSetAttribute(out_mma_kernel, cudaFuncAttributeMaxDynamicSharedMemorySize, OM_BYTES);

    // M = Wq @ Wk^T (180 x 1536), split-K x4
    gemm_nt<<<dim3(3, 24, 4), 256>>>(Wq, Wk, pMpart, IDIM, ADIM, ADIM / 4,
                                     ADIM, ADIM, 0LL, 0LL, 4);
    reduce_bt<<<dim3((IDIM * ADIM + 255) / 256, 1), 256>>>(pMpart, pM, IDIM * ADIM, 4);

    // G[b] = slots slots^T, split-K x8
    gemm_nt<<<dim3(1, 1, 64), 256>>>(slots, slots, pGpart, NS, NS, SDIM / 8,
                                     SDIM, SDIM, (long long)NS * SDIM, (long long)NS * SDIM, 8);
    reduce_bt<<<dim3((NS * NS + 255) / 256, NB), 256>>>(pGpart, pG, NS * NS, 8);

    // T[b] = M @ slots[b]^T, split-K x8; Tt = scale * T^T
    gemm_nt<<<dim3(3, 1, 64), 256>>>(pM, slots, pTpart, IDIM, NS, SDIM / 8,
                                     ADIM, SDIM, 0LL, (long long)NS * SDIM, 8);
    float scale = (float)(1.0 / sqrt((double)ADIM));
    reduce_T<<<dim3((IDIM * NS + 255) / 256, NB), 256>>>(scale);

    slot_means<<<NB, 256>>>(slots);
    split_slots<<<dim3(SDIM / 128, NB), 256>>>(slots);

    dots_kernel<<<dim3(NI / 32, NB), 256, DOTS_SMEM_BYTES>>>(x, g1v, b1v, out_w);

    out_mma_kernel<<<dim3(SDIM / 128, NI / 128, NB), 256, OM_BYTES>>>(g2v, b2v, out_s);
}